// round 1
// baseline (speedup 1.0000x reference)
#include <cuda_runtime.h>
#include <math.h>

// Problem constants
#define NE      800000
#define NNODE   50000
#define H       64
#define EF      32
#define C       160      // 2H + EF
#define C2      128      // 2H
#define TILE    64       // edges per block-tile
#define THREADS 512      // 16 warps, 4 edges/warp

struct __align__(16) Smem {
    float Wffw[C * C];    // [k][n] row-major, 102400 B
    float Wf[C2 * H];     // 32768 B
    float Ws[C2 * H];     // 32768 B
    float bffw[C];
    float bf[H];
    float bs[H];
    float x[TILE * C];    // gathered per-edge inputs [e][cat(z_src,z_dst,edge_attr)]
};

__global__ __launch_bounds__(THREADS, 1)
void decoder_edge_kernel(const float* __restrict__ z,
                         const float* __restrict__ ea,
                         const int*   __restrict__ srcp,
                         const int*   __restrict__ dstp,
                         const float* __restrict__ Wffw,
                         const float* __restrict__ bffw,
                         const float* __restrict__ Wf,
                         const float* __restrict__ bf,
                         const float* __restrict__ Ws,
                         const float* __restrict__ bs,
                         float* __restrict__ z_node,
                         float* __restrict__ z_edge)
{
    extern __shared__ char smem_raw[];
    Smem& s = *reinterpret_cast<Smem*>(smem_raw);

    // ---- cooperative weight load (once per CTA) ----
    {
        const float4* gw = reinterpret_cast<const float4*>(Wffw);
        float4* sw = reinterpret_cast<float4*>(s.Wffw);
        for (int i = threadIdx.x; i < (C * C) / 4; i += THREADS) sw[i] = gw[i];
        gw = reinterpret_cast<const float4*>(Wf);
        sw = reinterpret_cast<float4*>(s.Wf);
        for (int i = threadIdx.x; i < (C2 * H) / 4; i += THREADS) sw[i] = gw[i];
        gw = reinterpret_cast<const float4*>(Ws);
        sw = reinterpret_cast<float4*>(s.Ws);
        for (int i = threadIdx.x; i < (C2 * H) / 4; i += THREADS) sw[i] = gw[i];
        if (threadIdx.x < C)  s.bffw[threadIdx.x] = bffw[threadIdx.x];
        if (threadIdx.x >= 256 && threadIdx.x < 256 + H) s.bf[threadIdx.x - 256] = bf[threadIdx.x - 256];
        if (threadIdx.x >= 384 && threadIdx.x < 384 + H) s.bs[threadIdx.x - 384] = bs[threadIdx.x - 384];
    }

    const int warp = threadIdx.x >> 5;
    const int lane = threadIdx.x & 31;
    const int numTiles = NE / TILE;   // 12500 exact

    for (int tile = blockIdx.x; tile < numTiles; tile += gridDim.x) {
        const int e0 = tile * TILE;

        __syncthreads();   // previous iteration's readers done with s.x

        // ---- gather x tile: [TILE][160] = cat(z[src], z[dst], edge_attr) ----
        // 40 float4 per edge: q<16 -> z_src, q<32 -> z_dst, else edge_attr
        for (int idx = threadIdx.x; idx < TILE * 40; idx += THREADS) {
            const int e = idx / 40;
            const int q = idx - e * 40;
            const int ge = e0 + e;
            float4 v;
            if (q < 16) {
                v = reinterpret_cast<const float4*>(z + (size_t)srcp[ge] * H)[q];
            } else if (q < 32) {
                v = reinterpret_cast<const float4*>(z + (size_t)dstp[ge] * H)[q - 16];
            } else {
                v = reinterpret_cast<const float4*>(ea + (size_t)ge * EF)[q - 32];
            }
            reinterpret_cast<float4*>(&s.x[e * C])[q] = v;
        }
        __syncthreads();

        const int ew = warp * 4;     // this warp's 4 edges within the tile

        // ================= big branch: relu(x @ Wffw + b) =================
        float acc[4][5];
        #pragma unroll
        for (int j = 0; j < 5; j++) {
            const float b = s.bffw[lane + 32 * j];
            #pragma unroll
            for (int i = 0; i < 4; i++) acc[i][j] = b;
        }
        #pragma unroll 2
        for (int k4 = 0; k4 < C / 4; k4++) {
            float4 xv[4];
            #pragma unroll
            for (int i = 0; i < 4; i++)
                xv[i] = reinterpret_cast<const float4*>(&s.x[(ew + i) * C])[k4];
            #pragma unroll
            for (int kk = 0; kk < 4; kk++) {
                const int k = k4 * 4 + kk;
                float w[5];
                #pragma unroll
                for (int j = 0; j < 5; j++) w[j] = s.Wffw[k * C + lane + 32 * j];
                #pragma unroll
                for (int i = 0; i < 4; i++) {
                    const float xe = reinterpret_cast<const float*>(&xv[i])[kk];
                    #pragma unroll
                    for (int j = 0; j < 5; j++) acc[i][j] = fmaf(xe, w[j], acc[i][j]);
                }
            }
        }
        #pragma unroll
        for (int i = 0; i < 4; i++) {
            float* out = z_edge + (size_t)(e0 + ew + i) * C;
            #pragma unroll
            for (int j = 0; j < 5; j++)
                out[lane + 32 * j] = fmaxf(acc[i][j], 0.0f);
        }

        // ============== gate branch: m = cat(z_dst, z_src) ==============
        // m[k] = x[64+k] for k<64 else x[k-64]  (float4 idx: k4<16 -> 16+k4 else k4-16)
        float accf[4][2], accs[4][2];
        #pragma unroll
        for (int j = 0; j < 2; j++) {
            const float bfv = s.bf[lane + 32 * j];
            const float bsv = s.bs[lane + 32 * j];
            #pragma unroll
            for (int i = 0; i < 4; i++) { accf[i][j] = bfv; accs[i][j] = bsv; }
        }
        #pragma unroll 2
        for (int k4 = 0; k4 < C2 / 4; k4++) {
            const int xq = (k4 < 16) ? (16 + k4) : (k4 - 16);
            float4 mv[4];
            #pragma unroll
            for (int i = 0; i < 4; i++)
                mv[i] = reinterpret_cast<const float4*>(&s.x[(ew + i) * C])[xq];
            #pragma unroll
            for (int kk = 0; kk < 4; kk++) {
                const int k = k4 * 4 + kk;
                const float wf0 = s.Wf[k * H + lane];
                const float wf1 = s.Wf[k * H + lane + 32];
                const float ws0 = s.Ws[k * H + lane];
                const float ws1 = s.Ws[k * H + lane + 32];
                #pragma unroll
                for (int i = 0; i < 4; i++) {
                    const float m = reinterpret_cast<const float*>(&mv[i])[kk];
                    accf[i][0] = fmaf(m, wf0, accf[i][0]);
                    accf[i][1] = fmaf(m, wf1, accf[i][1]);
                    accs[i][0] = fmaf(m, ws0, accs[i][0]);
                    accs[i][1] = fmaf(m, ws1, accs[i][1]);
                }
            }
        }
        // sigmoid * softplus, scatter-add into z_node[dst]
        #pragma unroll
        for (int i = 0; i < 4; i++) {
            const int d = dstp[e0 + ew + i];
            float* nrow = z_node + (size_t)d * H;
            #pragma unroll
            for (int j = 0; j < 2; j++) {
                const float f  = accf[i][j];
                const float sv = accs[i][j];
                const float sig = 1.0f / (1.0f + expf(-f));
                const float sp  = fmaxf(sv, 0.0f) + log1pf(expf(-fabsf(sv)));
                atomicAdd(nrow + lane + 32 * j, sig * sp);
            }
        }
    }
}

extern "C" void kernel_launch(void* const* d_in, const int* in_sizes, int n_in,
                              void* d_out, int out_size)
{
    const float* z    = (const float*)d_in[0];   // [50000,64]
    const float* ea   = (const float*)d_in[1];   // [800000,32]
    const int*   eidx = (const int*)  d_in[2];   // [2,800000]
    const float* Wffw = (const float*)d_in[3];   // [160,160]
    const float* bffw = (const float*)d_in[4];   // [160]
    const float* Wf   = (const float*)d_in[5];   // [128,64]
    const float* bf   = (const float*)d_in[6];   // [64]
    const float* Ws   = (const float*)d_in[7];   // [128,64]
    const float* bs   = (const float*)d_in[8];   // [64]

    float* z_node = (float*)d_out;                       // [50000,64]
    float* z_edge = (float*)d_out + (size_t)NNODE * H;   // [800000,160]

    const int* srcp = eidx;        // row 0
    const int* dstp = eidx + NE;   // row 1

    // Residual base: z_node starts as z (output buffer is poisoned).
    cudaMemcpyAsync(z_node, z, (size_t)NNODE * H * sizeof(float),
                    cudaMemcpyDeviceToDevice, 0);

    const int smem = (int)sizeof(Smem);
    cudaFuncSetAttribute(decoder_edge_kernel,
                         cudaFuncAttributeMaxDynamicSharedMemorySize, smem);

    decoder_edge_kernel<<<152, THREADS, smem, 0>>>(
        z, ea, srcp, dstp, Wffw, bffw, Wf, bf, Ws, bs, z_node, z_edge);
}

// round 3
// speedup vs baseline: 2.4741x; 2.4741x over previous
#include <cuda_runtime.h>
#include <cuda_bf16.h>
#include <cstdint>
#include <math.h>

#define NE      800000
#define NNODE   50000
#define TILE    128
#define NT      (NE / TILE)     // 6250
#define THREADS 256

// ---------------- edge kernel SMEM (bytes) ----------------
#define XSTRIDE 336             // 160 bf16 cols padded to 168 (conflict-free ldmatrix)
#define WSTRIDE 336
#define E_XH    0
#define E_XL    (E_XH + 128 * XSTRIDE)      // 43008
#define E_WH    (E_XL + 128 * XSTRIDE)      // 86016
#define E_WL    (E_WH + 160 * WSTRIDE)      // 139776
#define E_BIAS  (E_WL + 160 * WSTRIDE)      // 193536
#define E_SMEM  (E_BIAS + 640)              // 194176

// ---------------- gate kernel SMEM ----------------
#define MSTRIDE 272             // 128 bf16 cols padded to 136
#define DSTRIDE 528             // 128 f32 cols padded to 132
#define G_M     0
#define G_W     (G_M + 128 * MSTRIDE)       // 34816
#define G_D     (G_W + 128 * MSTRIDE)       // 69632
#define G_LSIG  (G_D + 128 * DSTRIDE)       // 137216
#define G_LSP   (G_LSIG + 512 * 8)          // 141312
#define G_BF    (G_LSP + 512 * 8)           // 145408
#define G_BS    (G_BF + 256)
#define G_SMEM  (G_BS + 256)                // 145920

static __device__ __forceinline__ uint32_t smem_u32(const void* p) {
    uint32_t a;
    asm("{ .reg .u64 t; cvta.to.shared.u64 t, %1; cvt.u32.u64 %0, t; }" : "=r"(a) : "l"(p));
    return a;
}
static __device__ __forceinline__ void ldm_x4(uint32_t* r, uint32_t addr) {
    asm volatile("ldmatrix.sync.aligned.m8n8.x4.shared.b16 {%0,%1,%2,%3}, [%4];"
                 : "=r"(r[0]), "=r"(r[1]), "=r"(r[2]), "=r"(r[3]) : "r"(addr));
}
static __device__ __forceinline__ void ldm_x2t(uint32_t* r, uint32_t addr) {
    asm volatile("ldmatrix.sync.aligned.m8n8.x2.trans.shared.b16 {%0,%1}, [%2];"
                 : "=r"(r[0]), "=r"(r[1]) : "r"(addr));
}
static __device__ __forceinline__ void mma_bf16(float* c, const uint32_t* a, const uint32_t* b) {
    asm volatile("mma.sync.aligned.m16n8k16.row.col.f32.bf16.bf16.f32 "
                 "{%0,%1,%2,%3}, {%4,%5,%6,%7}, {%8,%9}, {%0,%1,%2,%3};"
                 : "+f"(c[0]), "+f"(c[1]), "+f"(c[2]), "+f"(c[3])
                 : "r"(a[0]), "r"(a[1]), "r"(a[2]), "r"(a[3]), "r"(b[0]), "r"(b[1]));
}
// pack (x0,x1) into bf16x2 hi word + residual lo word
static __device__ __forceinline__ void split2(float x0, float x1, uint32_t& hi, uint32_t& lo) {
    uint32_t h;
    asm("cvt.rn.bf16x2.f32 %0, %1, %2;" : "=r"(h) : "f"(x1), "f"(x0)); // first src -> upper
    float h0 = __uint_as_float(h << 16);
    float h1 = __uint_as_float(h & 0xFFFF0000u);
    uint32_t l;
    asm("cvt.rn.bf16x2.f32 %0, %1, %2;" : "=r"(l) : "f"(x1 - h1), "f"(x0 - h0));
    hi = h; lo = l;
}
static __device__ __forceinline__ uint32_t pack_bf16(float x0, float x1) {
    uint32_t h;
    asm("cvt.rn.bf16x2.f32 %0, %1, %2;" : "=r"(h) : "f"(x1), "f"(x0));
    return h;
}

// =====================================================================
// Kernel 1: z_edge = relu(cat(z_src, z_dst, ea) @ Wffw + b)   (3-product bf16)
// =====================================================================
__global__ __launch_bounds__(THREADS, 1)
void edge_mlp_kernel(const float* __restrict__ z,
                     const float* __restrict__ ea,
                     const int*   __restrict__ srcp,
                     const int*   __restrict__ dstp,
                     const float* __restrict__ W,
                     const float* __restrict__ bias,
                     float* __restrict__ z_edge)
{
    extern __shared__ char sm[];
    const uint32_t sb = smem_u32(sm);
    const int tid = threadIdx.x, wid = tid >> 5, lane = tid & 31;
    const int mi = wid >> 2, ni = wid & 3;

    // weights -> smem bf16 hi/lo, row-major [K=160][N=160], stride 336B
    for (int idx = tid; idx < 160 * 160; idx += THREADS) {
        const int k = idx / 160, n = idx - k * 160;
        const float w = W[idx];
        const __nv_bfloat16 h = __float2bfloat16(w);
        const __nv_bfloat16 l = __float2bfloat16(w - __bfloat162float(h));
        *reinterpret_cast<__nv_bfloat16*>(sm + E_WH + k * WSTRIDE + n * 2) = h;
        *reinterpret_cast<__nv_bfloat16*>(sm + E_WL + k * WSTRIDE + n * 2) = l;
    }
    if (tid < 160) reinterpret_cast<float*>(sm + E_BIAS)[tid] = bias[tid];

    const int e_loc = tid >> 1, half = tid & 1;
    const float* s_bias = reinterpret_cast<const float*>(sm + E_BIAS);

    for (int t = blockIdx.x; t < NT; t += gridDim.x) {
        __syncthreads();   // prior tile fully consumed (and init on first iter)

        // ---- gather x row halves: cols [0,80) or [80,160) ----
        {
            const int ge = t * TILE + e_loc;
            float4 v[20];
            if (half == 0) {
                const float4* zs = reinterpret_cast<const float4*>(z + (size_t)srcp[ge] * 64);
                const float4* zd = reinterpret_cast<const float4*>(z + (size_t)dstp[ge] * 64);
                #pragma unroll
                for (int i = 0; i < 16; i++) v[i] = zs[i];
                #pragma unroll
                for (int i = 0; i < 4; i++)  v[16 + i] = zd[i];
            } else {
                const float4* zd = reinterpret_cast<const float4*>(z + (size_t)dstp[ge] * 64);
                const float4* ep = reinterpret_cast<const float4*>(ea + (size_t)ge * 32);
                #pragma unroll
                for (int i = 0; i < 12; i++) v[i] = zd[4 + i];
                #pragma unroll
                for (int i = 0; i < 8; i++)  v[12 + i] = ep[i];
            }
            uint32_t* xh = reinterpret_cast<uint32_t*>(sm + E_XH + e_loc * XSTRIDE + half * 160);
            uint32_t* xl = reinterpret_cast<uint32_t*>(sm + E_XL + e_loc * XSTRIDE + half * 160);
            #pragma unroll
            for (int i = 0; i < 20; i++) {
                uint32_t h0, l0, h1, l1;
                split2(v[i].x, v[i].y, h0, l0);
                split2(v[i].z, v[i].w, h1, l1);
                xh[2 * i] = h0; xh[2 * i + 1] = h1;
                xl[2 * i] = l0; xl[2 * i + 1] = l1;
            }
        }
        __syncthreads();

        // ---- GEMM: warp (mi,ni) -> rows mi*64..+63, cols ni*40..+39 ----
        float acc[4][5][4];
        #pragma unroll
        for (int m = 0; m < 4; m++)
            #pragma unroll
            for (int n = 0; n < 5; n++)
                #pragma unroll
                for (int q = 0; q < 4; q++) acc[m][n][q] = 0.0f;

        #pragma unroll 2
        for (int k = 0; k < 10; k++) {
            uint32_t ah[4][4], al[4][4];
            const uint32_t arow = (uint32_t)(mi * 64 + (lane & 15)) * XSTRIDE
                                + (uint32_t)k * 32 + ((lane >> 4) << 4);
            #pragma unroll
            for (int m = 0; m < 4; m++) {
                ldm_x4(ah[m], sb + E_XH + arow + m * 16 * XSTRIDE);
                ldm_x4(al[m], sb + E_XL + arow + m * 16 * XSTRIDE);
            }
            const uint32_t brow = (uint32_t)(k * 16 + (lane & 15)) * WSTRIDE + (uint32_t)ni * 80;
            #pragma unroll
            for (int n = 0; n < 5; n++) {
                uint32_t bh[2], bl[2];
                ldm_x2t(bh, sb + E_WH + brow + n * 16);
                ldm_x2t(bl, sb + E_WL + brow + n * 16);
                #pragma unroll
                for (int m = 0; m < 4; m++) {
                    mma_bf16(acc[m][n], ah[m], bh);
                    mma_bf16(acc[m][n], al[m], bh);
                    mma_bf16(acc[m][n], ah[m], bl);
                }
            }
        }

        // ---- epilogue: bias + relu -> z_edge ----
        const int r0 = t * TILE + mi * 64 + (lane >> 2);
        #pragma unroll
        for (int n = 0; n < 5; n++) {
            const int col = ni * 40 + n * 8 + 2 * (lane & 3);
            const float b0 = s_bias[col], b1 = s_bias[col + 1];
            #pragma unroll
            for (int m = 0; m < 4; m++) {
                float* p0 = z_edge + (size_t)(r0 + m * 16) * 160 + col;
                float* p1 = z_edge + (size_t)(r0 + m * 16 + 8) * 160 + col;
                float2 o0, o1;
                o0.x = fmaxf(acc[m][n][0] + b0, 0.0f);
                o0.y = fmaxf(acc[m][n][1] + b1, 0.0f);
                o1.x = fmaxf(acc[m][n][2] + b0, 0.0f);
                o1.y = fmaxf(acc[m][n][3] + b1, 0.0f);
                *reinterpret_cast<float2*>(p0) = o0;
                *reinterpret_cast<float2*>(p1) = o1;
            }
        }
    }
}

// =====================================================================
// Kernel 2: msg = sigmoid(m@Wf+bf) * softplus(m@Ws+bs); z_node += scatter(msg)
//           m = cat(z_dst, z_src); single bf16 product; LUT nonlinearities
// =====================================================================
static __device__ __forceinline__ float lut_eval(const float2* tab, float x) {
    float tp = fmaf(x, 16.0f, 256.0f);            // (x+16)*16
    tp = fminf(fmaxf(tp, 0.0f), 511.0f);
    const int i = (int)tp;
    const float fr = tp - (float)i;
    const float2 c = tab[i];
    return fmaf(fr, c.y, c.x);
}

__global__ __launch_bounds__(THREADS, 1)
void gate_kernel(const float* __restrict__ z,
                 const int*   __restrict__ srcp,
                 const int*   __restrict__ dstp,
                 const float* __restrict__ Wf,
                 const float* __restrict__ bf,
                 const float* __restrict__ Ws,
                 const float* __restrict__ bs,
                 float* __restrict__ z_node)
{
    extern __shared__ char sm[];
    const uint32_t sb = smem_u32(sm);
    const int tid = threadIdx.x, wid = tid >> 5, lane = tid & 31;
    const int mi = wid >> 2, ni = wid & 3;

    // combined weights [K=128][N=128]: n<64 -> Wf, else Ws (bf16 hi only)
    for (int idx = tid; idx < 128 * 128; idx += THREADS) {
        const int k = idx >> 7, n = idx & 127;
        const float w = (n < 64) ? Wf[k * 64 + n] : Ws[k * 64 + (n - 64)];
        *reinterpret_cast<__nv_bfloat16*>(sm + G_W + k * MSTRIDE + n * 2) = __float2bfloat16(w);
    }
    // LUTs
    for (int i = tid; i < 512; i += THREADS) {
        const float x0 = -16.0f + (float)i * (1.0f / 16.0f);
        const float x1 = x0 + (1.0f / 16.0f);
        const float s0 = 1.0f / (1.0f + expf(-x0));
        const float s1 = 1.0f / (1.0f + expf(-x1));
        reinterpret_cast<float2*>(sm + G_LSIG)[i] = make_float2(s0, s1 - s0);
        const float p0 = fmaxf(x0, 0.0f) + log1pf(expf(-fabsf(x0)));
        const float p1 = fmaxf(x1, 0.0f) + log1pf(expf(-fabsf(x1)));
        reinterpret_cast<float2*>(sm + G_LSP)[i] = make_float2(p0, p1 - p0);
    }
    if (tid < 64) {
        reinterpret_cast<float*>(sm + G_BF)[tid] = bf[tid];
        reinterpret_cast<float*>(sm + G_BS)[tid] = bs[tid];
    }

    const float2* t_sig = reinterpret_cast<const float2*>(sm + G_LSIG);
    const float2* t_sp  = reinterpret_cast<const float2*>(sm + G_LSP);
    const float*  s_bf  = reinterpret_cast<const float*>(sm + G_BF);
    const float*  s_bs  = reinterpret_cast<const float*>(sm + G_BS);
    const int e_loc = tid >> 1, half = tid & 1;

    for (int t = blockIdx.x; t < NT; t += gridDim.x) {
        __syncthreads();

        // ---- gather m halves: half0 -> z_dst (cols 0-63), half1 -> z_src (64-127) ----
        {
            const int ge = t * TILE + e_loc;
            const int node = half ? srcp[ge] : dstp[ge];
            const float4* zr = reinterpret_cast<const float4*>(z + (size_t)node * 64);
            uint32_t* mh = reinterpret_cast<uint32_t*>(sm + G_M + e_loc * MSTRIDE + half * 128);
            #pragma unroll
            for (int i = 0; i < 16; i++) {
                const float4 v = zr[i];
                mh[2 * i]     = pack_bf16(v.x, v.y);
                mh[2 * i + 1] = pack_bf16(v.z, v.w);
            }
        }
        __syncthreads();

        // ---- GEMM: warp (mi,ni) -> rows mi*64..+63, cols ni*32..+31 ----
        float acc[4][4][4];
        #pragma unroll
        for (int m = 0; m < 4; m++)
            #pragma unroll
            for (int n = 0; n < 4; n++)
                #pragma unroll
                for (int q = 0; q < 4; q++) acc[m][n][q] = 0.0f;

        #pragma unroll 2
        for (int k = 0; k < 8; k++) {
            uint32_t a[4][4];
            const uint32_t arow = (uint32_t)(mi * 64 + (lane & 15)) * MSTRIDE
                                + (uint32_t)k * 32 + ((lane >> 4) << 4);
            #pragma unroll
            for (int m = 0; m < 4; m++) ldm_x4(a[m], sb + G_M + arow + m * 16 * MSTRIDE);
            const uint32_t brow = (uint32_t)(k * 16 + (lane & 15)) * MSTRIDE + (uint32_t)ni * 64;
            #pragma unroll
            for (int n = 0; n < 4; n++) {
                uint32_t b[2];
                ldm_x2t(b, sb + G_W + brow + n * 16);
                #pragma unroll
                for (int m = 0; m < 4; m++) mma_bf16(acc[m][n], a[m], b);
            }
        }

        // ---- stage D to smem for f/s pairing ----
        {
            const int rr = mi * 64 + (lane >> 2);
            #pragma unroll
            for (int n = 0; n < 4; n++) {
                const int col = ni * 32 + n * 8 + 2 * (lane & 3);
                #pragma unroll
                for (int m = 0; m < 4; m++) {
                    float* d0 = reinterpret_cast<float*>(sm + G_D + (rr + m * 16) * DSTRIDE) + col;
                    float* d1 = reinterpret_cast<float*>(sm + G_D + (rr + m * 16 + 8) * DSTRIDE) + col;
                    d0[0] = acc[m][n][0]; d0[1] = acc[m][n][1];
                    d1[0] = acc[m][n][2]; d1[1] = acc[m][n][3];
                }
            }
        }
        __syncthreads();

        // ---- gate + scatter: thread = (edge, col-half of 32) ----
        {
            const int ge = t * TILE + e_loc;
            const int dn = dstp[ge];
            const int c0 = half * 32;
            const float* drow = reinterpret_cast<const float*>(sm + G_D + e_loc * DSTRIDE);
            float* nrow = z_node + (size_t)dn * 64 + c0;
            #pragma unroll
            for (int j = 0; j < 8; j++) {
                const int c = c0 + 4 * j;
                const float4 f4 = *reinterpret_cast<const float4*>(drow + c);
                const float4 s4 = *reinterpret_cast<const float4*>(drow + 64 + c);
                float4 msg;
                {
                    const float f = f4.x + s_bf[c + 0], s = s4.x + s_bs[c + 0];
                    msg.x = lut_eval(t_sig, f) * fmaxf(lut_eval(t_sp, s), s);
                }
                {
                    const float f = f4.y + s_bf[c + 1], s = s4.y + s_bs[c + 1];
                    msg.y = lut_eval(t_sig, f) * fmaxf(lut_eval(t_sp, s), s);
                }
                {
                    const float f = f4.z + s_bf[c + 2], s = s4.z + s_bs[c + 2];
                    msg.z = lut_eval(t_sig, f) * fmaxf(lut_eval(t_sp, s), s);
                }
                {
                    const float f = f4.w + s_bf[c + 3], s = s4.w + s_bs[c + 3];
                    msg.w = lut_eval(t_sig, f) * fmaxf(lut_eval(t_sp, s), s);
                }
                atomicAdd(reinterpret_cast<float4*>(nrow + 4 * j), msg);
            }
        }
    }
}

extern "C" void kernel_launch(void* const* d_in, const int* in_sizes, int n_in,
                              void* d_out, int out_size)
{
    const float* z    = (const float*)d_in[0];
    const float* ea   = (const float*)d_in[1];
    const int*   eidx = (const int*)  d_in[2];
    const float* Wffw = (const float*)d_in[3];
    const float* bffw = (const float*)d_in[4];
    const float* Wf   = (const float*)d_in[5];
    const float* bf   = (const float*)d_in[6];
    const float* Ws   = (const float*)d_in[7];
    const float* bs   = (const float*)d_in[8];

    float* z_node = (float*)d_out;
    float* z_edge = (float*)d_out + (size_t)NNODE * 64;
    const int* srcp = eidx;
    const int* dstp = eidx + NE;

    // residual base for scatter-add
    cudaMemcpyAsync(z_node, z, (size_t)NNODE * 64 * sizeof(float),
                    cudaMemcpyDeviceToDevice, 0);

    cudaFuncSetAttribute(edge_mlp_kernel, cudaFuncAttributeMaxDynamicSharedMemorySize, E_SMEM);
    cudaFuncSetAttribute(gate_kernel,     cudaFuncAttributeMaxDynamicSharedMemorySize, G_SMEM);

    edge_mlp_kernel<<<148, THREADS, E_SMEM, 0>>>(z, ea, srcp, dstp, Wffw, bffw, z_edge);
    gate_kernel<<<148, THREADS, G_SMEM, 0>>>(z, srcp, dstp, Wf, bf, Ws, bs, z_node);
}